// round 15
// baseline (speedup 1.0000x reference)
#include <cuda_runtime.h>
#include <cuda_bf16.h>
#include <cstdint>

// Problem constants: B=32, S=2048, ENC=1024, DEC=1024
#define GB 32
#define GS 2048
#define GE 1024
#define GD 1024
#define GM (GB * GS)   // 65536 rows of enc_outputs

// -------- device scratch (allocation-free rule: __device__ globals) --------
__device__ float g_dec_proj[GB * GD];                          // 128 KB
__device__ float g_scores[GB * GS];                            // 256 KB
__device__ __align__(16) __nv_bfloat16 g_Bhi[GD * GE];         // 2 MB   W_enc^T hi
__device__ __align__(16) __nv_bfloat16 g_Blo[GD * GE];         // 2 MB   W_enc^T lo
__device__ __align__(16) __nv_bfloat16 g_Ahi[(size_t)GM * GE]; // 128 MB enc hi
__device__ __align__(16) __nv_bfloat16 g_Alo[(size_t)GM * GE]; // 128 MB enc lo

__device__ __forceinline__ void bf16_split(float x, unsigned short& h, unsigned short& l) {
    __nv_bfloat16 hb = __float2bfloat16(x);          // RN
    float res = x - __bfloat162float(hb);
    __nv_bfloat16 lb = __float2bfloat16(res);
    h = __bfloat16_as_ushort(hb);
    l = __bfloat16_as_ushort(lb);
}

// Branchless tanh, rel err ~2e-7. 2 MUFU + ~7 ALU, no divergence.
__device__ __forceinline__ float fast_tanh(float x) {
    const float e = __expf(-2.0f * fabsf(x));
    const float t = __fdividef(1.0f - e, 1.0f + e);
    return copysignf(t, x);
}

// m16n8k16 bf16 HMMA (baseline PTX)
#define MMA16816(C, A0, A1, A2, A3, B0, B1)                                   \
    asm volatile("mma.sync.aligned.m16n8k16.row.col.f32.bf16.bf16.f32 "       \
        "{%0,%1,%2,%3}, {%4,%5,%6,%7}, {%8,%9}, {%0,%1,%2,%3};"               \
        : "+f"((C)[0]), "+f"((C)[1]), "+f"((C)[2]), "+f"((C)[3])              \
        : "r"(A0), "r"(A1), "r"(A2), "r"(A3), "r"(B0), "r"(B1))

#define LDSM_X4(R, addr)                                                      \
    asm volatile("ldmatrix.sync.aligned.m8n8.x4.shared.b16 {%0,%1,%2,%3}, [%4];" \
        : "=r"((R)[0]), "=r"((R)[1]), "=r"((R)[2]), "=r"((R)[3]) : "r"(addr))

#define CP_ASYNC16(saddr, gptr)                                               \
    asm volatile("cp.async.cg.shared.global [%0], [%1], 16;"                  \
        :: "r"(saddr), "l"(gptr) : "memory")
#define CP_COMMIT()  asm volatile("cp.async.commit_group;" ::: "memory")
#define CP_WAIT2()   asm volatile("cp.async.wait_group 2;" ::: "memory")

__device__ __forceinline__ uint32_t smem_u32(const void* p) {
    uint32_t a;
    asm("{ .reg .u64 t; cvta.to.shared.u64 t, %1; cvt.u32.u64 %0, t; }"
        : "=r"(a) : "l"(p));
    return a;
}

// ================= fused prep kernel (init + prepB + dec_proj + prepA) ====
// 67840 blocks x 256 threads, branch by blockIdx.x:
//   [0, 256)        init: zero g_scores + ctx
//   [256, 1280)     prepB: W_enc fp32 -> transposed bf16 hi/lo [N, K]
//   [1280, 2304)    dec_proj: dec @ W_dec + bias (K split across 8 groups)
//   [2304, 67840)   prepA: enc fp32 -> bf16 hi/lo (bandwidth-dominant)
// Small latency-bound tasks occupy part of wave 1 and hide under prepA's
// HBM-bound waves; saves 3 launch boundaries + ~26 us of serial time.
#define PREP_BLOCKS (256 + 1024 + 1024 + GM * GE / 4 / 256)

__global__ __launch_bounds__(256)
void prep_fused_kernel(const float* __restrict__ enc,
                       const float* __restrict__ attnW,
                       const float* __restrict__ dec,
                       const float* __restrict__ bias,
                       float* __restrict__ ctx) {
    __shared__ float shm[1288];   // max(prepB tile 32x33=1056, sdec 1024 + part 264)
    const int bid = blockIdx.x;
    const int t   = threadIdx.x;

    if (bid >= 2304) {
        // ---- prepA: enc [GM, GE] fp32 -> bf16 hi/lo, same layout ----
        const size_t i = ((size_t)(bid - 2304) * 256 + t) * 4;
        float4 f = *(const float4*)(enc + i);
        unsigned short h0, h1, h2, h3, l0, l1, l2, l3;
        bf16_split(f.x, h0, l0); bf16_split(f.y, h1, l1);
        bf16_split(f.z, h2, l2); bf16_split(f.w, h3, l3);
        uint2 uh, ul;
        uh.x = (uint32_t)h0 | ((uint32_t)h1 << 16);
        uh.y = (uint32_t)h2 | ((uint32_t)h3 << 16);
        ul.x = (uint32_t)l0 | ((uint32_t)l1 << 16);
        ul.y = (uint32_t)l2 | ((uint32_t)l3 << 16);
        *(uint2*)((char*)g_Ahi + i * 2) = uh;
        *(uint2*)((char*)g_Alo + i * 2) = ul;
    } else if (bid < 256) {
        // ---- init: zero scores (65536) + ctx (first 32768) ----
        const int i = bid * 256 + t;
        g_scores[i] = 0.0f;
        if (i < GB * GD) ctx[i] = 0.0f;
    } else if (bid < 1280) {
        // ---- prepB: W_enc [K,N] -> transposed bf16 hi/lo [N,K] ----
        const float* Wenc = attnW + (size_t)GD * GD;
        const int pb = bid - 256;
        const int kb = (pb & 31) << 5;
        const int nb = (pb >> 5) << 5;
        const int tx = t & 31;
        const int ty = t >> 5;
        float (*tile)[33] = (float(*)[33])shm;
#pragma unroll
        for (int r = 0; r < 32; r += 8)
            tile[ty + r][tx] = Wenc[(size_t)(kb + ty + r) * GD + nb + tx];
        __syncthreads();
#pragma unroll
        for (int r = 0; r < 32; r += 8) {
            const int n = nb + ty + r;
            const int k = kb + tx;
            float x = tile[tx][ty + r];
            unsigned short h, l;
            bf16_split(x, h, l);
            g_Bhi[(size_t)n * GE + k] = __ushort_as_bfloat16(h);
            g_Blo[(size_t)n * GE + k] = __ushort_as_bfloat16(l);
        }
    } else {
        // ---- dec_proj: K split across 8 thread-groups, smem reduce ----
        const int pd = bid - 1280;
        const int b  = pd >> 5;
        const int d0 = (pd & 31) << 5;
        const int dl = t & 31;
        const int kg = t >> 5;
        float* sdec = shm;
        float (*part)[33] = (float(*)[33])(shm + 1024);

        for (int i = t; i < GD; i += 256) sdec[i] = dec[b * GD + i];
        __syncthreads();

        float acc = 0.0f;
        const float* Wp = attnW + (size_t)(kg * 128) * GD + d0 + dl;
        const float* sd = sdec + kg * 128;
#pragma unroll 8
        for (int e = 0; e < 128; e++)
            acc = fmaf(sd[e], Wp[(size_t)e * GD], acc);
        part[kg][dl] = acc;
        __syncthreads();

        if (t < 32) {
            float s = bias[d0 + t];
#pragma unroll
            for (int g = 0; g < 8; g++) s += part[g][t];
            g_dec_proj[b * GD + d0 + t] = s;
        }
    }
}

// ====================== HMMA scores GEMM (dominant) ========================
// BM=128, BN=128, BK=32. 512 threads = 16 warps (4m x 4n), warp tile 32x32.
// 3 mma passes: Ah*Bh + Ah*Bl + Al*Bh. All four tiles via cp.async, 4-stage
// circular pipeline (3 in flight, wait_group 2). Cross-stage fragment
// prefetch: ks0 fragments of stage t+1 load during stage t's ks1 MMA burst;
// the barrier sits between the two MMA bursts, not in front of loads.
// Fused epilogue: fast_tanh(acc+dec_proj)*v -> shfl reduce -> atomicAdd.

#define SKB    80                           // smem row stride bytes (40 bf16)
#define REG_SZ 10240                        // one region: 128 rows * 80 B
#define STG_SZ 40960                        // Ah | Al | Bh | Bl
#define NSTG   4
#define SM_DP  (NSTG * STG_SZ)              // 163840
#define SM_V   (SM_DP + 512)
#define GEMM_SMEM (SM_V + 512)              // 164864

__global__ __launch_bounds__(512, 1)
void scores_hmma_kernel(const float* __restrict__ vW)    // [GD]
{
    extern __shared__ char sm[];
    const uint32_t sm_u = smem_u32(sm);
    const int tid  = threadIdx.x;
    const int wid  = tid >> 5;
    const int lane = tid & 31;
    const int grp  = lane >> 2;          // 0..7
    const int tig  = lane & 3;           // 0..3
    const int wm   = wid >> 2;           // 0..3  (m warp)
    const int wn   = wid & 3;            // 0..3  (n warp)
    const int m8   = lane >> 3;          // ldmatrix matrix id 0..3
    const int ri   = lane & 7;           // ldmatrix row-in-matrix

    const int nblk = blockIdx.x & 7;
    const int mblk = blockIdx.x >> 3;
    const int row0 = mblk << 7;
    const int col0 = nblk << 7;
    const int b    = mblk >> 4;          // batch (16 M-tiles per batch)

    float* dp_s = (float*)(sm + SM_DP);
    float* v_s  = (float*)(sm + SM_V);
    if (tid < 128) {
        dp_s[tid] = g_dec_proj[b * GD + col0 + tid];
        v_s[tid]  = vW[col0 + tid];
    }

    // ---- cp.async mapping: each thread moves 1x16B per region per stage ---
    const int cprow = tid >> 2;              // 0..127
    const int cpch  = tid & 3;               // 16B chunk in 64B row
    const uint32_t sdst = sm_u + cprow * SKB + cpch * 16;
    const __nv_bfloat16* gAh = g_Ahi + (size_t)(row0 + cprow) * GE + cpch * 8;
    const __nv_bfloat16* gAl = g_Alo + (size_t)(row0 + cprow) * GE + cpch * 8;
    const __nv_bfloat16* gBh = g_Bhi + (size_t)(col0 + cprow) * GE + cpch * 8;
    const __nv_bfloat16* gBl = g_Blo + (size_t)(col0 + cprow) * GE + cpch * 8;

    auto issue_cp = [&](int stg, int k0) {
        const uint32_t d = sdst + stg * STG_SZ;
        CP_ASYNC16(d,              (const void*)(gAh + k0));
        CP_ASYNC16(d + REG_SZ,     (const void*)(gAl + k0));
        CP_ASYNC16(d + 2 * REG_SZ, (const void*)(gBh + k0));
        CP_ASYNC16(d + 3 * REG_SZ, (const void*)(gBl + k0));
    };

    // ---- ldmatrix base addresses ----
    const uint32_t aLd = sm_u + (wm * 32 + (m8 & 1) * 8 + ri) * SKB + (m8 >> 1) * 16;
    const uint32_t bLd = sm_u + 2 * REG_SZ +
                         (wn * 32 + (m8 >> 1) * 8 + ri) * SKB + (m8 & 1) * 16;

    float acc[2][4][4];
#pragma unroll
    for (int mi = 0; mi < 2; mi++)
#pragma unroll
        for (int ni = 0; ni < 4; ni++)
#pragma unroll
            for (int j = 0; j < 4; j++) acc[mi][ni][j] = 0.0f;

    uint32_t aH[2][2][4], aL[2][2][4], bH[2][2][4], bL[2][2][4]; // [fbuf][mi/np][4]

    auto ldfrags = [&](int fb, uint32_t aB, uint32_t bB, int ks) {
        const uint32_t ko = ks * 32;
        LDSM_X4(aH[fb][0], aB + ko);
        LDSM_X4(aH[fb][1], aB + 1280 + ko);            // +16 rows
        LDSM_X4(aL[fb][0], aB + REG_SZ + ko);
        LDSM_X4(aL[fb][1], aB + REG_SZ + 1280 + ko);
        LDSM_X4(bH[fb][0], bB + ko);
        LDSM_X4(bH[fb][1], bB + 1280 + ko);            // +16 n
        LDSM_X4(bL[fb][0], bB + REG_SZ + ko);
        LDSM_X4(bL[fb][1], bB + REG_SZ + 1280 + ko);
    };
    auto domma = [&](int fb) {
#pragma unroll
        for (int np = 0; np < 2; np++)
#pragma unroll
            for (int sub = 0; sub < 2; sub++) {
                const int ni = np * 2 + sub;
                const uint32_t bh0 = bH[fb][np][sub * 2], bh1 = bH[fb][np][sub * 2 + 1];
                const uint32_t bl0 = bL[fb][np][sub * 2], bl1 = bL[fb][np][sub * 2 + 1];
#pragma unroll
                for (int mi = 0; mi < 2; mi++) {
                    MMA16816(acc[mi][ni], aH[fb][mi][0], aH[fb][mi][1], aH[fb][mi][2], aH[fb][mi][3], bh0, bh1);
                    MMA16816(acc[mi][ni], aH[fb][mi][0], aH[fb][mi][1], aH[fb][mi][2], aH[fb][mi][3], bl0, bl1);
                    MMA16816(acc[mi][ni], aL[fb][mi][0], aL[fb][mi][1], aL[fb][mi][2], aL[fb][mi][3], bh0, bh1);
                }
            }
    };

    // ---- prologue: 3 stages in flight; preload stage-0 ks0 fragments ------
    issue_cp(0, 0);  CP_COMMIT();
    issue_cp(1, 32); CP_COMMIT();
    issue_cp(2, 64); CP_COMMIT();
    CP_WAIT2();                          // stage 0 resident
    __syncthreads();
    ldfrags(0, aLd, bLd, 0);

    int stg = 0;
    for (int t = 0; t < 32; t++) {
        const uint32_t aB = aLd + stg * STG_SZ;
        const uint32_t bB = bLd + stg * STG_SZ;
        ldfrags(1, aB, bB, 1);           // ks1 fragments of stage t
        if (t + 3 < 32) {                // refill slot (t+3)%4 (= stage t-1's
            int ns = stg + 3; if (ns >= NSTG) ns -= NSTG;   // slot, reads done
            issue_cp(ns, (t + 3) << 5);                     // per prior barrier)
        }
        CP_COMMIT();                     // one group per iteration (may be empty)
        domma(0);                        // ks0 MMA burst (fragments preloaded)
        if (t < 31) {
            CP_WAIT2();                  // stage t+1 resident (<=2 groups pending)
            __syncthreads();             // all warps done reading stage t smem
            int ns = stg + 1; if (ns >= NSTG) ns -= NSTG;
            ldfrags(0, aLd + ns * STG_SZ, bLd + ns * STG_SZ, 0);  // prefetch
            stg = ns;                    // (overlaps with ks1 MMA burst below)
        }
        domma(1);                        // ks1 MMA burst
    }

    // ---- fused epilogue: fast_tanh(acc + dec_proj) * v, reduce, atomic ----
    float rp[4] = {0.f, 0.f, 0.f, 0.f};
#pragma unroll
    for (int mi = 0; mi < 2; mi++)
#pragma unroll
        for (int ni = 0; ni < 4; ni++) {
            const int cl = wn * 32 + ni * 8 + tig * 2;
            const float d0 = dp_s[cl],     v0 = v_s[cl];
            const float d1 = dp_s[cl + 1], v1 = v_s[cl + 1];
            rp[mi * 2 + 0] += fast_tanh(acc[mi][ni][0] + d0) * v0
                            + fast_tanh(acc[mi][ni][1] + d1) * v1;
            rp[mi * 2 + 1] += fast_tanh(acc[mi][ni][2] + d0) * v0
                            + fast_tanh(acc[mi][ni][3] + d1) * v1;
        }
#pragma unroll
    for (int j = 0; j < 4; j++) {
        rp[j] += __shfl_xor_sync(0xffffffffu, rp[j], 1);
        rp[j] += __shfl_xor_sync(0xffffffffu, rp[j], 2);
    }
    if (tig == 0) {
        const int rbase = row0 + wm * 32 + grp;
        atomicAdd(&g_scores[rbase],      rp[0]);
        atomicAdd(&g_scores[rbase + 8],  rp[1]);
        atomicAdd(&g_scores[rbase + 16], rp[2]);
        atomicAdd(&g_scores[rbase + 24], rp[3]);
    }
}

// ============================ softmax + context ============================
__global__ void softmax_kernel(const int* __restrict__ mask,
                               float* __restrict__ attn) {
    __shared__ float sv[GS];
    __shared__ float red[8];
    const int b = blockIdx.x;
    const int t = threadIdx.x;

    float m = -3.4e38f;
    for (int s = t; s < GS; s += 256) {
        float v = g_scores[b * GS + s];
        v = (mask[b * GS + s] != 0) ? v : -10000.0f;
        sv[s] = v;
        m = fmaxf(m, v);
    }
#pragma unroll
    for (int off = 16; off > 0; off >>= 1)
        m = fmaxf(m, __shfl_xor_sync(0xffffffffu, m, off));
    if ((t & 31) == 0) red[t >> 5] = m;
    __syncthreads();
    if (t < 8) {
        float x = red[t];
#pragma unroll
        for (int off = 4; off > 0; off >>= 1)
            x = fmaxf(x, __shfl_xor_sync(0xffu, x, off));
        if (t == 0) red[0] = x;
    }
    __syncthreads();
    m = red[0];
    __syncthreads();

    float sum = 0.0f;
    for (int s = t; s < GS; s += 256) {
        float e = __expf(sv[s] - m);
        sv[s] = e;
        sum += e;
    }
#pragma unroll
    for (int off = 16; off > 0; off >>= 1)
        sum += __shfl_xor_sync(0xffffffffu, sum, off);
    if ((t & 31) == 0) red[t >> 5] = sum;
    __syncthreads();
    if (t < 8) {
        float x = red[t];
#pragma unroll
        for (int off = 4; off > 0; off >>= 1)
            x += __shfl_xor_sync(0xffu, x, off);
        if (t == 0) red[0] = x;
    }
    __syncthreads();
    const float inv = 1.0f / red[0];

    for (int s = t; s < GS; s += 256)
        attn[b * GS + s] = sv[s] * inv;
}

__global__ void context_kernel(const float* __restrict__ enc,
                               const float* __restrict__ attn,
                               float* __restrict__ ctx) {
    __shared__ float w[128];
    const int sc = blockIdx.x;
    const int b  = blockIdx.y;
    const int t  = threadIdx.x;

    if (t < 128) w[t] = attn[b * GS + sc * 128 + t];
    __syncthreads();

    const float* ep = enc + ((size_t)b * GS + sc * 128) * GE;
    float a0 = 0.f, a1 = 0.f, a2 = 0.f, a3 = 0.f;
#pragma unroll 4
    for (int s = 0; s < 128; s++) {
        const float ws = w[s];
        const float* p = ep + (size_t)s * GE + t;
        a0 = fmaf(ws, p[0],   a0);
        a1 = fmaf(ws, p[256], a1);
        a2 = fmaf(ws, p[512], a2);
        a3 = fmaf(ws, p[768], a3);
    }
    atomicAdd(&ctx[b * GD + t],       a0);
    atomicAdd(&ctx[b * GD + 256 + t], a1);
    atomicAdd(&ctx[b * GD + 512 + t], a2);
    atomicAdd(&ctx[b * GD + 768 + t], a3);
}

// ============================ kernel_launch ================================
// Inputs identified BY ELEMENT COUNT (robust to ordering):
//   enc 67108864, attn_W 2097152, dec 32768, mask 65536 (int32, bool-conv),
//   attn_b / v_W both 1024 (keep relative order).
extern "C" void kernel_launch(void* const* d_in, const int* in_sizes, int n_in,
                              void* d_out, int out_size) {
    const float* dec   = nullptr;
    const float* enc   = nullptr;
    const int*   mask  = nullptr;
    const float* attnW = nullptr;
    const float* attnB = nullptr;
    const float* vW    = nullptr;

    for (int i = 0; i < n_in; i++) {
        switch (in_sizes[i]) {
            case GM * GE:     enc   = (const float*)d_in[i]; break;
            case 2 * GD * GD: attnW = (const float*)d_in[i]; break;
            case GB * GD:     dec   = (const float*)d_in[i]; break;
            case GB * GS:     mask  = (const int*)d_in[i];   break;
            case GD:
                if (!attnB) attnB = (const float*)d_in[i];
                else        vW    = (const float*)d_in[i];
                break;
            default: break;
        }
    }

    float* ctx  = (float*)d_out;             // [32,1024]
    float* attn = (float*)d_out + GB * GD;   // [32,2048]

    cudaFuncSetAttribute(scores_hmma_kernel,
                         cudaFuncAttributeMaxDynamicSharedMemorySize,
                         GEMM_SMEM);

    prep_fused_kernel<<<PREP_BLOCKS, 256>>>(enc, attnW, dec, attnB, ctx);
    scores_hmma_kernel<<<(GM / 128) * (GD / 128), 512, GEMM_SMEM>>>(vW);
    softmax_kernel<<<GB, 256>>>(mask, attn);
    context_kernel<<<dim3(GS / 128, GB), 256>>>(enc, attn, ctx);
}

// round 16
// speedup vs baseline: 1.4899x; 1.4899x over previous
#include <cuda_runtime.h>
#include <cuda_bf16.h>
#include <cstdint>

// Problem constants: B=32, S=2048, ENC=1024, DEC=1024
#define GB 32
#define GS 2048
#define GE 1024
#define GD 1024
#define GM (GB * GS)   // 65536 rows of enc_outputs

// -------- device scratch (allocation-free rule: __device__ globals) --------
__device__ float g_dec_proj[GB * GD];                          // 128 KB
__device__ float g_scores[GB * GS];                            // 256 KB
__device__ __align__(16) __nv_bfloat16 g_Bhi[GD * GE];         // 2 MB   W_enc^T hi
__device__ __align__(16) __nv_bfloat16 g_Blo[GD * GE];         // 2 MB   W_enc^T lo
__device__ __align__(16) __nv_bfloat16 g_Ahi[(size_t)GM * GE]; // 128 MB enc hi
__device__ __align__(16) __nv_bfloat16 g_Alo[(size_t)GM * GE]; // 128 MB enc lo

__device__ __forceinline__ void bf16_split(float x, unsigned short& h, unsigned short& l) {
    __nv_bfloat16 hb = __float2bfloat16(x);          // RN
    float res = x - __bfloat162float(hb);
    __nv_bfloat16 lb = __float2bfloat16(res);
    h = __bfloat16_as_ushort(hb);
    l = __bfloat16_as_ushort(lb);
}

// Branchless tanh, rel err ~2e-7. 2 MUFU + ~7 ALU, no divergence.
__device__ __forceinline__ float fast_tanh(float x) {
    const float e = __expf(-2.0f * fabsf(x));
    const float t = __fdividef(1.0f - e, 1.0f + e);
    return copysignf(t, x);
}

// m16n8k16 bf16 HMMA (baseline PTX)
#define MMA16816(C, A0, A1, A2, A3, B0, B1)                                   \
    asm volatile("mma.sync.aligned.m16n8k16.row.col.f32.bf16.bf16.f32 "       \
        "{%0,%1,%2,%3}, {%4,%5,%6,%7}, {%8,%9}, {%0,%1,%2,%3};"               \
        : "+f"((C)[0]), "+f"((C)[1]), "+f"((C)[2]), "+f"((C)[3])              \
        : "r"(A0), "r"(A1), "r"(A2), "r"(A3), "r"(B0), "r"(B1))

#define LDSM_X4(R, addr)                                                      \
    asm volatile("ldmatrix.sync.aligned.m8n8.x4.shared.b16 {%0,%1,%2,%3}, [%4];" \
        : "=r"((R)[0]), "=r"((R)[1]), "=r"((R)[2]), "=r"((R)[3]) : "r"(addr))

#define CP_ASYNC16(saddr, gptr)                                               \
    asm volatile("cp.async.cg.shared.global [%0], [%1], 16;"                  \
        :: "r"(saddr), "l"(gptr) : "memory")
#define CP_COMMIT()  asm volatile("cp.async.commit_group;" ::: "memory")
#define CP_WAIT2()   asm volatile("cp.async.wait_group 2;" ::: "memory")

__device__ __forceinline__ uint32_t smem_u32(const void* p) {
    uint32_t a;
    asm("{ .reg .u64 t; cvta.to.shared.u64 t, %1; cvt.u32.u64 %0, t; }"
        : "=r"(a) : "l"(p));
    return a;
}

// ============ prepA: standalone, R14-proven shape (512 thr, 0 smem) ========
__global__ __launch_bounds__(512)
void prepA_kernel(const float* __restrict__ enc) {
    const size_t i = ((size_t)blockIdx.x * 512 + threadIdx.x) * 4;
    float4 f = *(const float4*)(enc + i);
    unsigned short h0, h1, h2, h3, l0, l1, l2, l3;
    bf16_split(f.x, h0, l0); bf16_split(f.y, h1, l1);
    bf16_split(f.z, h2, l2); bf16_split(f.w, h3, l3);
    uint2 uh, ul;
    uh.x = (uint32_t)h0 | ((uint32_t)h1 << 16);
    uh.y = (uint32_t)h2 | ((uint32_t)h3 << 16);
    ul.x = (uint32_t)l0 | ((uint32_t)l1 << 16);
    ul.y = (uint32_t)l2 | ((uint32_t)l3 << 16);
    *(uint2*)((char*)g_Ahi + i * 2) = uh;
    *(uint2*)((char*)g_Alo + i * 2) = ul;
}

// ===== small_fused: init + prepB + dec_proj (2304 blocks x 256 threads) ====
// Per-branch code and thread mappings identical to the standalone R14
// kernels; only the launch boundary is removed. No bandwidth-bound blocks.
__global__ __launch_bounds__(256)
void small_fused_kernel(const float* __restrict__ attnW,
                        const float* __restrict__ dec,
                        const float* __restrict__ bias,
                        float* __restrict__ ctx) {
    __shared__ float shm[1288];   // max(prepB tile 32x33, sdec 1024 + part 8x33)
    const int bid = blockIdx.x;
    const int t   = threadIdx.x;

    if (bid < 256) {
        // ---- init: zero scores (65536) + ctx (first 32768) ----
        const int i = bid * 256 + t;
        g_scores[i] = 0.0f;
        if (i < GB * GD) ctx[i] = 0.0f;
    } else if (bid < 1280) {
        // ---- prepB: W_enc [K,N] -> transposed bf16 hi/lo [N,K] ----
        const float* Wenc = attnW + (size_t)GD * GD;
        const int pb = bid - 256;
        const int kb = (pb & 31) << 5;
        const int nb = (pb >> 5) << 5;
        const int tx = t & 31;
        const int ty = t >> 5;
        float (*tile)[33] = (float(*)[33])shm;
#pragma unroll
        for (int r = 0; r < 32; r += 8)
            tile[ty + r][tx] = Wenc[(size_t)(kb + ty + r) * GD + nb + tx];
        __syncthreads();
#pragma unroll
        for (int r = 0; r < 32; r += 8) {
            const int n = nb + ty + r;
            const int k = kb + tx;
            float x = tile[tx][ty + r];
            unsigned short h, l;
            bf16_split(x, h, l);
            g_Bhi[(size_t)n * GE + k] = __ushort_as_bfloat16(h);
            g_Blo[(size_t)n * GE + k] = __ushort_as_bfloat16(l);
        }
    } else {
        // ---- dec_proj: K split across 8 thread-groups, smem reduce ----
        const int pd = bid - 1280;
        const int b  = pd >> 5;
        const int d0 = (pd & 31) << 5;
        const int dl = t & 31;
        const int kg = t >> 5;
        float* sdec = shm;
        float (*part)[33] = (float(*)[33])(shm + 1024);

        for (int i = t; i < GD; i += 256) sdec[i] = dec[b * GD + i];
        __syncthreads();

        float acc = 0.0f;
        const float* Wp = attnW + (size_t)(kg * 128) * GD + d0 + dl;
        const float* sd = sdec + kg * 128;
#pragma unroll 8
        for (int e = 0; e < 128; e++)
            acc = fmaf(sd[e], Wp[(size_t)e * GD], acc);
        part[kg][dl] = acc;
        __syncthreads();

        if (t < 32) {
            float s = bias[d0 + t];
#pragma unroll
            for (int g = 0; g < 8; g++) s += part[g][t];
            g_dec_proj[b * GD + d0 + t] = s;
        }
    }
}

// ====================== HMMA scores GEMM (dominant) ========================
// BM=128, BN=128, BK=32. 512 threads = 16 warps (4m x 4n), warp tile 32x32.
// 3 mma passes: Ah*Bh + Ah*Bl + Al*Bh. All four tiles via cp.async, 4-stage
// circular pipeline (3 in flight, wait_group 2). Cross-stage fragment
// prefetch: ks0 fragments of stage t+1 load during stage t's ks1 MMA burst;
// the barrier sits between the two MMA bursts, not in front of loads.
// Fused epilogue: fast_tanh(acc+dec_proj)*v -> shfl reduce -> atomicAdd.

#define SKB    80                           // smem row stride bytes (40 bf16)
#define REG_SZ 10240                        // one region: 128 rows * 80 B
#define STG_SZ 40960                        // Ah | Al | Bh | Bl
#define NSTG   4
#define SM_DP  (NSTG * STG_SZ)              // 163840
#define SM_V   (SM_DP + 512)
#define GEMM_SMEM (SM_V + 512)              // 164864

__global__ __launch_bounds__(512, 1)
void scores_hmma_kernel(const float* __restrict__ vW)    // [GD]
{
    extern __shared__ char sm[];
    const uint32_t sm_u = smem_u32(sm);
    const int tid  = threadIdx.x;
    const int wid  = tid >> 5;
    const int lane = tid & 31;
    const int grp  = lane >> 2;          // 0..7
    const int tig  = lane & 3;           // 0..3
    const int wm   = wid >> 2;           // 0..3  (m warp)
    const int wn   = wid & 3;            // 0..3  (n warp)
    const int m8   = lane >> 3;          // ldmatrix matrix id 0..3
    const int ri   = lane & 7;           // ldmatrix row-in-matrix

    const int nblk = blockIdx.x & 7;
    const int mblk = blockIdx.x >> 3;
    const int row0 = mblk << 7;
    const int col0 = nblk << 7;
    const int b    = mblk >> 4;          // batch (16 M-tiles per batch)

    float* dp_s = (float*)(sm + SM_DP);
    float* v_s  = (float*)(sm + SM_V);
    if (tid < 128) {
        dp_s[tid] = g_dec_proj[b * GD + col0 + tid];
        v_s[tid]  = vW[col0 + tid];
    }

    // ---- cp.async mapping: each thread moves 1x16B per region per stage ---
    const int cprow = tid >> 2;              // 0..127
    const int cpch  = tid & 3;               // 16B chunk in 64B row
    const uint32_t sdst = sm_u + cprow * SKB + cpch * 16;
    const __nv_bfloat16* gAh = g_Ahi + (size_t)(row0 + cprow) * GE + cpch * 8;
    const __nv_bfloat16* gAl = g_Alo + (size_t)(row0 + cprow) * GE + cpch * 8;
    const __nv_bfloat16* gBh = g_Bhi + (size_t)(col0 + cprow) * GE + cpch * 8;
    const __nv_bfloat16* gBl = g_Blo + (size_t)(col0 + cprow) * GE + cpch * 8;

    auto issue_cp = [&](int stg, int k0) {
        const uint32_t d = sdst + stg * STG_SZ;
        CP_ASYNC16(d,              (const void*)(gAh + k0));
        CP_ASYNC16(d + REG_SZ,     (const void*)(gAl + k0));
        CP_ASYNC16(d + 2 * REG_SZ, (const void*)(gBh + k0));
        CP_ASYNC16(d + 3 * REG_SZ, (const void*)(gBl + k0));
    };

    // ---- ldmatrix base addresses ----
    const uint32_t aLd = sm_u + (wm * 32 + (m8 & 1) * 8 + ri) * SKB + (m8 >> 1) * 16;
    const uint32_t bLd = sm_u + 2 * REG_SZ +
                         (wn * 32 + (m8 >> 1) * 8 + ri) * SKB + (m8 & 1) * 16;

    float acc[2][4][4];
#pragma unroll
    for (int mi = 0; mi < 2; mi++)
#pragma unroll
        for (int ni = 0; ni < 4; ni++)
#pragma unroll
            for (int j = 0; j < 4; j++) acc[mi][ni][j] = 0.0f;

    uint32_t aH[2][2][4], aL[2][2][4], bH[2][2][4], bL[2][2][4]; // [fbuf][mi/np][4]

    auto ldfrags = [&](int fb, uint32_t aB, uint32_t bB, int ks) {
        const uint32_t ko = ks * 32;
        LDSM_X4(aH[fb][0], aB + ko);
        LDSM_X4(aH[fb][1], aB + 1280 + ko);            // +16 rows
        LDSM_X4(aL[fb][0], aB + REG_SZ + ko);
        LDSM_X4(aL[fb][1], aB + REG_SZ + 1280 + ko);
        LDSM_X4(bH[fb][0], bB + ko);
        LDSM_X4(bH[fb][1], bB + 1280 + ko);            // +16 n
        LDSM_X4(bL[fb][0], bB + REG_SZ + ko);
        LDSM_X4(bL[fb][1], bB + REG_SZ + 1280 + ko);
    };
    auto domma = [&](int fb) {
#pragma unroll
        for (int np = 0; np < 2; np++)
#pragma unroll
            for (int sub = 0; sub < 2; sub++) {
                const int ni = np * 2 + sub;
                const uint32_t bh0 = bH[fb][np][sub * 2], bh1 = bH[fb][np][sub * 2 + 1];
                const uint32_t bl0 = bL[fb][np][sub * 2], bl1 = bL[fb][np][sub * 2 + 1];
#pragma unroll
                for (int mi = 0; mi < 2; mi++) {
                    MMA16816(acc[mi][ni], aH[fb][mi][0], aH[fb][mi][1], aH[fb][mi][2], aH[fb][mi][3], bh0, bh1);
                    MMA16816(acc[mi][ni], aH[fb][mi][0], aH[fb][mi][1], aH[fb][mi][2], aH[fb][mi][3], bl0, bl1);
                    MMA16816(acc[mi][ni], aL[fb][mi][0], aL[fb][mi][1], aL[fb][mi][2], aL[fb][mi][3], bh0, bh1);
                }
            }
    };

    // ---- prologue: 3 stages in flight; preload stage-0 ks0 fragments ------
    issue_cp(0, 0);  CP_COMMIT();
    issue_cp(1, 32); CP_COMMIT();
    issue_cp(2, 64); CP_COMMIT();
    CP_WAIT2();                          // stage 0 resident
    __syncthreads();
    ldfrags(0, aLd, bLd, 0);

    int stg = 0;
    for (int t = 0; t < 32; t++) {
        const uint32_t aB = aLd + stg * STG_SZ;
        const uint32_t bB = bLd + stg * STG_SZ;
        ldfrags(1, aB, bB, 1);           // ks1 fragments of stage t
        if (t + 3 < 32) {                // refill slot (t+3)%4 (= stage t-1's
            int ns = stg + 3; if (ns >= NSTG) ns -= NSTG;   // slot, reads done
            issue_cp(ns, (t + 3) << 5);                     // per prior barrier)
        }
        CP_COMMIT();                     // one group per iteration (may be empty)
        domma(0);                        // ks0 MMA burst (fragments preloaded)
        if (t < 31) {
            CP_WAIT2();                  // stage t+1 resident (<=2 groups pending)
            __syncthreads();             // all warps done reading stage t smem
            int ns = stg + 1; if (ns >= NSTG) ns -= NSTG;
            ldfrags(0, aLd + ns * STG_SZ, bLd + ns * STG_SZ, 0);  // prefetch
            stg = ns;                    // (overlaps with ks1 MMA burst below)
        }
        domma(1);                        // ks1 MMA burst
    }

    // ---- fused epilogue: fast_tanh(acc + dec_proj) * v, reduce, atomic ----
    float rp[4] = {0.f, 0.f, 0.f, 0.f};
#pragma unroll
    for (int mi = 0; mi < 2; mi++)
#pragma unroll
        for (int ni = 0; ni < 4; ni++) {
            const int cl = wn * 32 + ni * 8 + tig * 2;
            const float d0 = dp_s[cl],     v0 = v_s[cl];
            const float d1 = dp_s[cl + 1], v1 = v_s[cl + 1];
            rp[mi * 2 + 0] += fast_tanh(acc[mi][ni][0] + d0) * v0
                            + fast_tanh(acc[mi][ni][1] + d1) * v1;
            rp[mi * 2 + 1] += fast_tanh(acc[mi][ni][2] + d0) * v0
                            + fast_tanh(acc[mi][ni][3] + d1) * v1;
        }
#pragma unroll
    for (int j = 0; j < 4; j++) {
        rp[j] += __shfl_xor_sync(0xffffffffu, rp[j], 1);
        rp[j] += __shfl_xor_sync(0xffffffffu, rp[j], 2);
    }
    if (tig == 0) {
        const int rbase = row0 + wm * 32 + grp;
        atomicAdd(&g_scores[rbase],      rp[0]);
        atomicAdd(&g_scores[rbase + 8],  rp[1]);
        atomicAdd(&g_scores[rbase + 16], rp[2]);
        atomicAdd(&g_scores[rbase + 24], rp[3]);
    }
}

// ============================ softmax + context ============================
__global__ void softmax_kernel(const int* __restrict__ mask,
                               float* __restrict__ attn) {
    __shared__ float sv[GS];
    __shared__ float red[8];
    const int b = blockIdx.x;
    const int t = threadIdx.x;

    float m = -3.4e38f;
    for (int s = t; s < GS; s += 256) {
        float v = g_scores[b * GS + s];
        v = (mask[b * GS + s] != 0) ? v : -10000.0f;
        sv[s] = v;
        m = fmaxf(m, v);
    }
#pragma unroll
    for (int off = 16; off > 0; off >>= 1)
        m = fmaxf(m, __shfl_xor_sync(0xffffffffu, m, off));
    if ((t & 31) == 0) red[t >> 5] = m;
    __syncthreads();
    if (t < 8) {
        float x = red[t];
#pragma unroll
        for (int off = 4; off > 0; off >>= 1)
            x = fmaxf(x, __shfl_xor_sync(0xffu, x, off));
        if (t == 0) red[0] = x;
    }
    __syncthreads();
    m = red[0];
    __syncthreads();

    float sum = 0.0f;
    for (int s = t; s < GS; s += 256) {
        float e = __expf(sv[s] - m);
        sv[s] = e;
        sum += e;
    }
#pragma unroll
    for (int off = 16; off > 0; off >>= 1)
        sum += __shfl_xor_sync(0xffffffffu, sum, off);
    if ((t & 31) == 0) red[t >> 5] = sum;
    __syncthreads();
    if (t < 8) {
        float x = red[t];
#pragma unroll
        for (int off = 4; off > 0; off >>= 1)
            x += __shfl_xor_sync(0xffu, x, off);
        if (t == 0) red[0] = x;
    }
    __syncthreads();
    const float inv = 1.0f / red[0];

    for (int s = t; s < GS; s += 256)
        attn[b * GS + s] = sv[s] * inv;
}

__global__ void context_kernel(const float* __restrict__ enc,
                               const float* __restrict__ attn,
                               float* __restrict__ ctx) {
    __shared__ float w[128];
    const int sc = blockIdx.x;
    const int b  = blockIdx.y;
    const int t  = threadIdx.x;

    if (t < 128) w[t] = attn[b * GS + sc * 128 + t];
    __syncthreads();

    const float* ep = enc + ((size_t)b * GS + sc * 128) * GE;
    float a0 = 0.f, a1 = 0.f, a2 = 0.f, a3 = 0.f;
#pragma unroll 4
    for (int s = 0; s < 128; s++) {
        const float ws = w[s];
        const float* p = ep + (size_t)s * GE + t;
        a0 = fmaf(ws, p[0],   a0);
        a1 = fmaf(ws, p[256], a1);
        a2 = fmaf(ws, p[512], a2);
        a3 = fmaf(ws, p[768], a3);
    }
    atomicAdd(&ctx[b * GD + t],       a0);
    atomicAdd(&ctx[b * GD + 256 + t], a1);
    atomicAdd(&ctx[b * GD + 512 + t], a2);
    atomicAdd(&ctx[b * GD + 768 + t], a3);
}

// ============================ kernel_launch ================================
// Inputs identified BY ELEMENT COUNT (robust to ordering):
//   enc 67108864, attn_W 2097152, dec 32768, mask 65536 (int32, bool-conv),
//   attn_b / v_W both 1024 (keep relative order).
extern "C" void kernel_launch(void* const* d_in, const int* in_sizes, int n_in,
                              void* d_out, int out_size) {
    const float* dec   = nullptr;
    const float* enc   = nullptr;
    const int*   mask  = nullptr;
    const float* attnW = nullptr;
    const float* attnB = nullptr;
    const float* vW    = nullptr;

    for (int i = 0; i < n_in; i++) {
        switch (in_sizes[i]) {
            case GM * GE:     enc   = (const float*)d_in[i]; break;
            case 2 * GD * GD: attnW = (const float*)d_in[i]; break;
            case GB * GD:     dec   = (const float*)d_in[i]; break;
            case GB * GS:     mask  = (const int*)d_in[i];   break;
            case GD:
                if (!attnB) attnB = (const float*)d_in[i];
                else        vW    = (const float*)d_in[i];
                break;
            default: break;
        }
    }

    float* ctx  = (float*)d_out;             // [32,1024]
    float* attn = (float*)d_out + GB * GD;   // [32,2048]

    cudaFuncSetAttribute(scores_hmma_kernel,
                         cudaFuncAttributeMaxDynamicSharedMemorySize,
                         GEMM_SMEM);

    prepA_kernel<<<GM * (GE / 4) / 512, 512>>>(enc);
    small_fused_kernel<<<2304, 256>>>(attnW, dec, attnB, ctx);
    scores_hmma_kernel<<<(GM / 128) * (GD / 128), 512, GEMM_SMEM>>>(vW);
    softmax_kernel<<<GB, 256>>>(mask, attn);
    context_kernel<<<dim3(GS / 128, GB), 256>>>(enc, attn, ctx);
}

// round 17
// speedup vs baseline: 1.4903x; 1.0003x over previous
#include <cuda_runtime.h>
#include <cuda_bf16.h>
#include <cstdint>

// Problem constants: B=32, S=2048, ENC=1024, DEC=1024
#define GB 32
#define GS 2048
#define GE 1024
#define GD 1024
#define GM (GB * GS)   // 65536 rows of enc_outputs

// -------- device scratch (allocation-free rule: __device__ globals) --------
__device__ float g_dec_proj[GB * GD];                          // 128 KB
__device__ float g_scores[GB * GS];                            // 256 KB
__device__ __align__(16) __nv_bfloat16 g_Bhi[GD * GE];         // 2 MB   W_enc^T hi
__device__ __align__(16) __nv_bfloat16 g_Blo[GD * GE];         // 2 MB   W_enc^T lo
__device__ __align__(16) __nv_bfloat16 g_Ahi[(size_t)GM * GE]; // 128 MB enc hi
__device__ __align__(16) __nv_bfloat16 g_Alo[(size_t)GM * GE]; // 128 MB enc lo

__device__ __forceinline__ void bf16_split(float x, unsigned short& h, unsigned short& l) {
    __nv_bfloat16 hb = __float2bfloat16(x);          // RN
    float res = x - __bfloat162float(hb);
    __nv_bfloat16 lb = __float2bfloat16(res);
    h = __bfloat16_as_ushort(hb);
    l = __bfloat16_as_ushort(lb);
}

// Branchless tanh, rel err ~2e-7. 2 MUFU + ~7 ALU, no divergence.
__device__ __forceinline__ float fast_tanh(float x) {
    const float e = __expf(-2.0f * fabsf(x));
    const float t = __fdividef(1.0f - e, 1.0f + e);
    return copysignf(t, x);
}

// m16n8k16 bf16 HMMA (baseline PTX)
#define MMA16816(C, A0, A1, A2, A3, B0, B1)                                   \
    asm volatile("mma.sync.aligned.m16n8k16.row.col.f32.bf16.bf16.f32 "       \
        "{%0,%1,%2,%3}, {%4,%5,%6,%7}, {%8,%9}, {%0,%1,%2,%3};"               \
        : "+f"((C)[0]), "+f"((C)[1]), "+f"((C)[2]), "+f"((C)[3])              \
        : "r"(A0), "r"(A1), "r"(A2), "r"(A3), "r"(B0), "r"(B1))

#define LDSM_X4(R, addr)                                                      \
    asm volatile("ldmatrix.sync.aligned.m8n8.x4.shared.b16 {%0,%1,%2,%3}, [%4];" \
        : "=r"((R)[0]), "=r"((R)[1]), "=r"((R)[2]), "=r"((R)[3]) : "r"(addr))

#define CP_ASYNC16(saddr, gptr)                                               \
    asm volatile("cp.async.cg.shared.global [%0], [%1], 16;"                  \
        :: "r"(saddr), "l"(gptr) : "memory")
#define CP_COMMIT()  asm volatile("cp.async.commit_group;" ::: "memory")
#define CP_WAIT2()   asm volatile("cp.async.wait_group 2;" ::: "memory")

__device__ __forceinline__ uint32_t smem_u32(const void* p) {
    uint32_t a;
    asm("{ .reg .u64 t; cvta.to.shared.u64 t, %1; cvt.u32.u64 %0, t; }"
        : "=r"(a) : "l"(p));
    return a;
}

// ============ prepA: standalone, R14-proven shape (512 thr, 0 smem) ========
__global__ __launch_bounds__(512)
void prepA_kernel(const float* __restrict__ enc) {
    const size_t i = ((size_t)blockIdx.x * 512 + threadIdx.x) * 4;
    float4 f = *(const float4*)(enc + i);
    unsigned short h0, h1, h2, h3, l0, l1, l2, l3;
    bf16_split(f.x, h0, l0); bf16_split(f.y, h1, l1);
    bf16_split(f.z, h2, l2); bf16_split(f.w, h3, l3);
    uint2 uh, ul;
    uh.x = (uint32_t)h0 | ((uint32_t)h1 << 16);
    uh.y = (uint32_t)h2 | ((uint32_t)h3 << 16);
    ul.x = (uint32_t)l0 | ((uint32_t)l1 << 16);
    ul.y = (uint32_t)l2 | ((uint32_t)l3 << 16);
    *(uint2*)((char*)g_Ahi + i * 2) = uh;
    *(uint2*)((char*)g_Alo + i * 2) = ul;
}

// ===== small_fused: init + prepB + dec_proj (2304 blocks x 256 threads) ====
__global__ __launch_bounds__(256)
void small_fused_kernel(const float* __restrict__ attnW,
                        const float* __restrict__ dec,
                        const float* __restrict__ bias,
                        float* __restrict__ ctx) {
    __shared__ float shm[1288];   // max(prepB tile 32x33, sdec 1024 + part 8x33)
    const int bid = blockIdx.x;
    const int t   = threadIdx.x;

    if (bid < 256) {
        // ---- init: zero scores (65536) + ctx (first 32768) ----
        const int i = bid * 256 + t;
        g_scores[i] = 0.0f;
        if (i < GB * GD) ctx[i] = 0.0f;
    } else if (bid < 1280) {
        // ---- prepB: W_enc [K,N] -> transposed bf16 hi/lo [N,K] ----
        const float* Wenc = attnW + (size_t)GD * GD;
        const int pb = bid - 256;
        const int kb = (pb & 31) << 5;
        const int nb = (pb >> 5) << 5;
        const int tx = t & 31;
        const int ty = t >> 5;
        float (*tile)[33] = (float(*)[33])shm;
#pragma unroll
        for (int r = 0; r < 32; r += 8)
            tile[ty + r][tx] = Wenc[(size_t)(kb + ty + r) * GD + nb + tx];
        __syncthreads();
#pragma unroll
        for (int r = 0; r < 32; r += 8) {
            const int n = nb + ty + r;
            const int k = kb + tx;
            float x = tile[tx][ty + r];
            unsigned short h, l;
            bf16_split(x, h, l);
            g_Bhi[(size_t)n * GE + k] = __ushort_as_bfloat16(h);
            g_Blo[(size_t)n * GE + k] = __ushort_as_bfloat16(l);
        }
    } else {
        // ---- dec_proj: K split across 8 thread-groups, smem reduce ----
        const int pd = bid - 1280;
        const int b  = pd >> 5;
        const int d0 = (pd & 31) << 5;
        const int dl = t & 31;
        const int kg = t >> 5;
        float* sdec = shm;
        float (*part)[33] = (float(*)[33])(shm + 1024);

        for (int i = t; i < GD; i += 256) sdec[i] = dec[b * GD + i];
        __syncthreads();

        float acc = 0.0f;
        const float* Wp = attnW + (size_t)(kg * 128) * GD + d0 + dl;
        const float* sd = sdec + kg * 128;
#pragma unroll 8
        for (int e = 0; e < 128; e++)
            acc = fmaf(sd[e], Wp[(size_t)e * GD], acc);
        part[kg][dl] = acc;
        __syncthreads();

        if (t < 32) {
            float s = bias[d0 + t];
#pragma unroll
            for (int g = 0; g < 8; g++) s += part[g][t];
            g_dec_proj[b * GD + d0 + t] = s;
        }
    }
}

// ====================== HMMA scores GEMM (dominant) ========================
// BM=128, BN=128, BK=32. 512 threads = 16 warps (4m x 4n), warp tile 32x32.
// 3 mma passes: Ah*Bh + Ah*Bl + Al*Bh. All four tiles via cp.async, 4-stage
// circular pipeline (3 in flight, wait_group 2). Cross-stage fragment
// prefetch; barrier between the two MMA bursts.
// Fused epilogue: fast_tanh(acc+dec_proj)*v -> shfl reduce -> atomicAdd.

#define SKB    80                           // smem row stride bytes (40 bf16)
#define REG_SZ 10240                        // one region: 128 rows * 80 B
#define STG_SZ 40960                        // Ah | Al | Bh | Bl
#define NSTG   4
#define SM_DP  (NSTG * STG_SZ)              // 163840
#define SM_V   (SM_DP + 512)
#define GEMM_SMEM (SM_V + 512)              // 164864

__global__ __launch_bounds__(512, 1)
void scores_hmma_kernel(const float* __restrict__ vW)    // [GD]
{
    extern __shared__ char sm[];
    const uint32_t sm_u = smem_u32(sm);
    const int tid  = threadIdx.x;
    const int wid  = tid >> 5;
    const int lane = tid & 31;
    const int grp  = lane >> 2;          // 0..7
    const int tig  = lane & 3;           // 0..3
    const int wm   = wid >> 2;           // 0..3  (m warp)
    const int wn   = wid & 3;            // 0..3  (n warp)
    const int m8   = lane >> 3;          // ldmatrix matrix id 0..3
    const int ri   = lane & 7;           // ldmatrix row-in-matrix

    const int nblk = blockIdx.x & 7;
    const int mblk = blockIdx.x >> 3;
    const int row0 = mblk << 7;
    const int col0 = nblk << 7;
    const int b    = mblk >> 4;          // batch (16 M-tiles per batch)

    float* dp_s = (float*)(sm + SM_DP);
    float* v_s  = (float*)(sm + SM_V);
    if (tid < 128) {
        dp_s[tid] = g_dec_proj[b * GD + col0 + tid];
        v_s[tid]  = vW[col0 + tid];
    }

    // ---- cp.async mapping: each thread moves 1x16B per region per stage ---
    const int cprow = tid >> 2;              // 0..127
    const int cpch  = tid & 3;               // 16B chunk in 64B row
    const uint32_t sdst = sm_u + cprow * SKB + cpch * 16;
    const __nv_bfloat16* gAh = g_Ahi + (size_t)(row0 + cprow) * GE + cpch * 8;
    const __nv_bfloat16* gAl = g_Alo + (size_t)(row0 + cprow) * GE + cpch * 8;
    const __nv_bfloat16* gBh = g_Bhi + (size_t)(col0 + cprow) * GE + cpch * 8;
    const __nv_bfloat16* gBl = g_Blo + (size_t)(col0 + cprow) * GE + cpch * 8;

    auto issue_cp = [&](int stg, int k0) {
        const uint32_t d = sdst + stg * STG_SZ;
        CP_ASYNC16(d,              (const void*)(gAh + k0));
        CP_ASYNC16(d + REG_SZ,     (const void*)(gAl + k0));
        CP_ASYNC16(d + 2 * REG_SZ, (const void*)(gBh + k0));
        CP_ASYNC16(d + 3 * REG_SZ, (const void*)(gBl + k0));
    };

    // ---- ldmatrix base addresses ----
    const uint32_t aLd = sm_u + (wm * 32 + (m8 & 1) * 8 + ri) * SKB + (m8 >> 1) * 16;
    const uint32_t bLd = sm_u + 2 * REG_SZ +
                         (wn * 32 + (m8 >> 1) * 8 + ri) * SKB + (m8 & 1) * 16;

    float acc[2][4][4];
#pragma unroll
    for (int mi = 0; mi < 2; mi++)
#pragma unroll
        for (int ni = 0; ni < 4; ni++)
#pragma unroll
            for (int j = 0; j < 4; j++) acc[mi][ni][j] = 0.0f;

    uint32_t aH[2][2][4], aL[2][2][4], bH[2][2][4], bL[2][2][4]; // [fbuf][mi/np][4]

    auto ldfrags = [&](int fb, uint32_t aB, uint32_t bB, int ks) {
        const uint32_t ko = ks * 32;
        LDSM_X4(aH[fb][0], aB + ko);
        LDSM_X4(aH[fb][1], aB + 1280 + ko);            // +16 rows
        LDSM_X4(aL[fb][0], aB + REG_SZ + ko);
        LDSM_X4(aL[fb][1], aB + REG_SZ + 1280 + ko);
        LDSM_X4(bH[fb][0], bB + ko);
        LDSM_X4(bH[fb][1], bB + 1280 + ko);            // +16 n
        LDSM_X4(bL[fb][0], bB + REG_SZ + ko);
        LDSM_X4(bL[fb][1], bB + REG_SZ + 1280 + ko);
    };
    auto domma = [&](int fb) {
#pragma unroll
        for (int np = 0; np < 2; np++)
#pragma unroll
            for (int sub = 0; sub < 2; sub++) {
                const int ni = np * 2 + sub;
                const uint32_t bh0 = bH[fb][np][sub * 2], bh1 = bH[fb][np][sub * 2 + 1];
                const uint32_t bl0 = bL[fb][np][sub * 2], bl1 = bL[fb][np][sub * 2 + 1];
#pragma unroll
                for (int mi = 0; mi < 2; mi++) {
                    MMA16816(acc[mi][ni], aH[fb][mi][0], aH[fb][mi][1], aH[fb][mi][2], aH[fb][mi][3], bh0, bh1);
                    MMA16816(acc[mi][ni], aH[fb][mi][0], aH[fb][mi][1], aH[fb][mi][2], aH[fb][mi][3], bl0, bl1);
                    MMA16816(acc[mi][ni], aL[fb][mi][0], aL[fb][mi][1], aL[fb][mi][2], aL[fb][mi][3], bh0, bh1);
                }
            }
    };

    // ---- prologue: 3 stages in flight; preload stage-0 ks0 fragments ------
    issue_cp(0, 0);  CP_COMMIT();
    issue_cp(1, 32); CP_COMMIT();
    issue_cp(2, 64); CP_COMMIT();
    CP_WAIT2();                          // stage 0 resident
    __syncthreads();
    ldfrags(0, aLd, bLd, 0);

    int stg = 0;
    for (int t = 0; t < 32; t++) {
        const uint32_t aB = aLd + stg * STG_SZ;
        const uint32_t bB = bLd + stg * STG_SZ;
        ldfrags(1, aB, bB, 1);           // ks1 fragments of stage t
        if (t + 3 < 32) {                // refill slot (t+3)%4 (= stage t-1's
            int ns = stg + 3; if (ns >= NSTG) ns -= NSTG;   // slot, reads done
            issue_cp(ns, (t + 3) << 5);                     // per prior barrier)
        }
        CP_COMMIT();                     // one group per iteration (may be empty)
        domma(0);                        // ks0 MMA burst (fragments preloaded)
        if (t < 31) {
            CP_WAIT2();                  // stage t+1 resident (<=2 groups pending)
            __syncthreads();             // all warps done reading stage t smem
            int ns = stg + 1; if (ns >= NSTG) ns -= NSTG;
            ldfrags(0, aLd + ns * STG_SZ, bLd + ns * STG_SZ, 0);  // prefetch
            stg = ns;                    // (overlaps with ks1 MMA burst below)
        }
        domma(1);                        // ks1 MMA burst
    }

    // ---- fused epilogue: fast_tanh(acc + dec_proj) * v, reduce, atomic ----
    float rp[4] = {0.f, 0.f, 0.f, 0.f};
#pragma unroll
    for (int mi = 0; mi < 2; mi++)
#pragma unroll
        for (int ni = 0; ni < 4; ni++) {
            const int cl = wn * 32 + ni * 8 + tig * 2;
            const float d0 = dp_s[cl],     v0 = v_s[cl];
            const float d1 = dp_s[cl + 1], v1 = v_s[cl + 1];
            rp[mi * 2 + 0] += fast_tanh(acc[mi][ni][0] + d0) * v0
                            + fast_tanh(acc[mi][ni][1] + d1) * v1;
            rp[mi * 2 + 1] += fast_tanh(acc[mi][ni][2] + d0) * v0
                            + fast_tanh(acc[mi][ni][3] + d1) * v1;
        }
#pragma unroll
    for (int j = 0; j < 4; j++) {
        rp[j] += __shfl_xor_sync(0xffffffffu, rp[j], 1);
        rp[j] += __shfl_xor_sync(0xffffffffu, rp[j], 2);
    }
    if (tig == 0) {
        const int rbase = row0 + wm * 32 + grp;
        atomicAdd(&g_scores[rbase],      rp[0]);
        atomicAdd(&g_scores[rbase + 8],  rp[1]);
        atomicAdd(&g_scores[rbase + 16], rp[2]);
        atomicAdd(&g_scores[rbase + 24], rp[3]);
    }
}

// ============================ softmax + context ============================
// softmax: 1024 threads/block (was 256) — 32 CTAs are latency-bound; wider
// blocks cut the strided-loop trip count 8 -> 2 and deepen per-SM issue.
__global__ __launch_bounds__(1024)
void softmax_kernel(const int* __restrict__ mask,
                    float* __restrict__ attn) {
    __shared__ float sv[GS];
    __shared__ float red[32];
    const int b = blockIdx.x;
    const int t = threadIdx.x;

    float m = -3.4e38f;
    for (int s = t; s < GS; s += 1024) {
        float v = g_scores[b * GS + s];
        v = (mask[b * GS + s] != 0) ? v : -10000.0f;
        sv[s] = v;
        m = fmaxf(m, v);
    }
#pragma unroll
    for (int off = 16; off > 0; off >>= 1)
        m = fmaxf(m, __shfl_xor_sync(0xffffffffu, m, off));
    if ((t & 31) == 0) red[t >> 5] = m;
    __syncthreads();
    if (t < 32) {
        float x = red[t];
#pragma unroll
        for (int off = 16; off > 0; off >>= 1)
            x = fmaxf(x, __shfl_xor_sync(0xffffffffu, x, off));
        if (t == 0) red[0] = x;
    }
    __syncthreads();
    m = red[0];
    __syncthreads();

    float sum = 0.0f;
    for (int s = t; s < GS; s += 1024) {
        float e = __expf(sv[s] - m);
        sv[s] = e;
        sum += e;
    }
#pragma unroll
    for (int off = 16; off > 0; off >>= 1)
        sum += __shfl_xor_sync(0xffffffffu, sum, off);
    if ((t & 31) == 0) red[t >> 5] = sum;
    __syncthreads();
    if (t < 32) {
        float x = red[t];
#pragma unroll
        for (int off = 16; off > 0; off >>= 1)
            x += __shfl_xor_sync(0xffffffffu, x, off);
        if (t == 0) red[0] = x;
    }
    __syncthreads();
    const float inv = 1.0f / red[0];

    for (int s = t; s < GS; s += 1024)
        attn[b * GS + s] = sv[s] * inv;
}

// context: s-chunks of 64 (grid 1024 CTAs, was 512) — more CTAs/SM raises
// in-flight loads toward the LTS cap (was DRAM=70%, occ=40%).
__global__ void context_kernel(const float* __restrict__ enc,
                               const float* __restrict__ attn,
                               float* __restrict__ ctx) {
    __shared__ float w[64];
    const int sc = blockIdx.x;
    const int b  = blockIdx.y;
    const int t  = threadIdx.x;

    if (t < 64) w[t] = attn[b * GS + sc * 64 + t];
    __syncthreads();

    const float* ep = enc + ((size_t)b * GS + sc * 64) * GE;
    float a0 = 0.f, a1 = 0.f, a2 = 0.f, a3 = 0.f;
#pragma unroll 4
    for (int s = 0; s < 64; s++) {
        const float ws = w[s];
        const float* p = ep + (size_t)s * GE + t;
        a0 = fmaf(ws, p[0],   a0);
        a1 = fmaf(ws, p[256], a1);
        a2 = fmaf(ws, p[512], a2);
        a3 = fmaf(ws, p[768], a3);
    }
    atomicAdd(&ctx[b * GD + t],       a0);
    atomicAdd(&ctx[b * GD + 256 + t], a1);
    atomicAdd(&ctx[b * GD + 512 + t], a2);
    atomicAdd(&ctx[b * GD + 768 + t], a3);
}

// ============================ kernel_launch ================================
// Inputs identified BY ELEMENT COUNT (robust to ordering):
//   enc 67108864, attn_W 2097152, dec 32768, mask 65536 (int32, bool-conv),
//   attn_b / v_W both 1024 (keep relative order).
extern "C" void kernel_launch(void* const* d_in, const int* in_sizes, int n_in,
                              void* d_out, int out_size) {
    const float* dec   = nullptr;
    const float* enc   = nullptr;
    const int*   mask  = nullptr;
    const float* attnW = nullptr;
    const float* attnB = nullptr;
    const float* vW    = nullptr;

    for (int i = 0; i < n_in; i++) {
        switch (in_sizes[i]) {
            case GM * GE:     enc   = (const float*)d_in[i]; break;
            case 2 * GD * GD: attnW = (const float*)d_in[i]; break;
            case GB * GD:     dec   = (const float*)d_in[i]; break;
            case GB * GS:     mask  = (const int*)d_in[i];   break;
            case GD:
                if (!attnB) attnB = (const float*)d_in[i];
                else        vW    = (const float*)d_in[i];
                break;
            default: break;
        }
    }

    float* ctx  = (float*)d_out;             // [32,1024]
    float* attn = (float*)d_out + GB * GD;   // [32,2048]

    cudaFuncSetAttribute(scores_hmma_kernel,
                         cudaFuncAttributeMaxDynamicSharedMemorySize,
                         GEMM_SMEM);

    prepA_kernel<<<GM * (GE / 4) / 512, 512>>>(enc);
    small_fused_kernel<<<2304, 256>>>(attnW, dec, attnB, ctx);
    scores_hmma_kernel<<<(GM / 128) * (GD / 128), 512, GEMM_SMEM>>>(vW);
    softmax_kernel<<<GB, 1024>>>(mask, attn);
    context_kernel<<<dim3(GS / 64, GB), 256>>>(enc, attn, ctx);
}